// round 11
// baseline (speedup 1.0000x reference)
#include <cuda_runtime.h>
#include <cuda_fp16.h>
#include <float.h>
#include <cstdint>

#define B_   16
#define S_   512
#define D_   768
#define H_   12
#define HD_  64
#define K_   16
#define NS_  128
#define R_   32
#define BS_  (B_*S_)
#define Z_   (B_*H_)

// ================= PTX helpers =================
__device__ __forceinline__ uint32_t smem_to_u32(const void* p) {
    uint32_t a;
    asm("{ .reg .u64 t; cvta.to.shared.u64 t, %1; cvt.u32.u64 %0, t; }" : "=r"(a) : "l"(p));
    return a;
}
__device__ __forceinline__ void cpa16(uint32_t dst, const void* src) {
    asm volatile("cp.async.ca.shared.global [%0], [%1], 16;" :: "r"(dst), "l"(src));
}
__device__ __forceinline__ void ldsm4(uint32_t* r, uint32_t addr) {
    asm volatile("ldmatrix.sync.aligned.m8n8.x4.shared.b16 {%0,%1,%2,%3}, [%4];"
        : "=r"(r[0]), "=r"(r[1]), "=r"(r[2]), "=r"(r[3]) : "r"(addr));
}
__device__ __forceinline__ void ldsm2(uint32_t* r, uint32_t addr) {
    asm volatile("ldmatrix.sync.aligned.m8n8.x2.shared.b16 {%0,%1}, [%2];"
        : "=r"(r[0]), "=r"(r[1]) : "r"(addr));
}
__device__ __forceinline__ void ldsm4t(uint32_t* r, uint32_t addr) {
    asm volatile("ldmatrix.sync.aligned.m8n8.x4.trans.shared.b16 {%0,%1,%2,%3}, [%4];"
        : "=r"(r[0]), "=r"(r[1]), "=r"(r[2]), "=r"(r[3]) : "r"(addr));
}
__device__ __forceinline__ void mma16816(float* c, const uint32_t* a, const uint32_t* b) {
    asm volatile("mma.sync.aligned.m16n8k16.row.col.f32.f16.f16.f32 "
        "{%0,%1,%2,%3}, {%4,%5,%6,%7}, {%8,%9}, {%0,%1,%2,%3};"
        : "+f"(c[0]), "+f"(c[1]), "+f"(c[2]), "+f"(c[3])
        : "r"(a[0]), "r"(a[1]), "r"(a[2]), "r"(a[3]), "r"(b[0]), "r"(b[1]));
}

// ================= scratch =================
__device__ float    g_xnorm[BS_];
__device__ double   g_sum[B_], g_sumsq[B_];
__device__ unsigned g_minb[B_], g_maxb[B_];
__device__ float    g_dist[B_*S_*NS_];
__device__ float    g_topo[B_*D_];
__device__ __align__(16) __half g_xpack [BS_*D_];
__device__ __align__(16) __half g_qkvpack[(size_t)BS_*3*D_];
__device__ __align__(16) __half g_opack [BS_*D_];
__device__ float    g_attnP[BS_*D_];
__device__ float    g_x1[BS_*D_];
__device__ __align__(16) __half g_x1pack[BS_*D_];
__device__ __align__(16) __half g_hpack [(size_t)BS_*2*D_];
__device__ float    g_ffn2[BS_*D_];
__device__ __align__(16) __half g_wqkvh[D_*3*D_];     // [K][N] fp16
__device__ __align__(16) __half g_wouth[D_*D_];
__device__ __align__(16) __half g_wf1h [D_*2*D_];
__device__ __align__(16) __half g_wf2h [2*D_*D_];

// ================= HMMA GEMM (3-stage pipeline, BK=64) =================
// C[128,BN] = A[M,K] * B.  BNN=true: B stored [K][N]; false: B stored [N][K].
// GATHER (NT only): B row index comes from sidx[n0+r].
// EPI: 0=+bias, 1=gelu, 2=*alpha, 3=cdist.
template<int BN, int EPI, bool PACKOUT, bool BNN, bool GATHER>
__global__ __launch_bounds__(256,2)
void hgemm(const __half* __restrict__ A, const __half* __restrict__ Bm,
           void* __restrict__ Cv, const float* __restrict__ bias,
           int M, int Kd, int lda, int ldb, int ldc,
           int Hdiv, long sAb, long sAh, long sBb, long sBh, long sCb, long sCh,
           float alpha, const float* __restrict__ xn, const int* __restrict__ sidx)
{
    constexpr int NT = BN/32;
    constexpr int NW = BN/4;
    constexpr int AH = 128*72;                 // halfs per A stage (BK=64 + 8 pad)
    constexpr int BH = BNN ? 64*136 : BN*72;   // halfs per B stage
    constexpr int NSTG = 3;
    extern __shared__ __half dsm[];

    const int tid = threadIdx.x, warp = tid>>5, lane = tid&31;
    const int wm = (warp>>2)*64, wn = (warp&3)*NW;
    const int z = blockIdx.z, zb = z/Hdiv, zh = z - zb*Hdiv;
    A  += zb*sAb + zh*sAh;
    Bm += zb*sBb + zh*sBh;
    const int n0 = blockIdx.x*BN, m0 = blockIdx.y*128;
    const uint32_t sa = smem_to_u32(dsm);
    const uint32_t sb = sa + NSTG*AH*2;

    float acc[4][NT][4];
    #pragma unroll
    for (int i=0;i<4;i++)
        #pragma unroll
        for (int j=0;j<NT;j++)
            #pragma unroll
            for (int q=0;q<4;q++) acc[i][j][q]=0.f;

    const int nch = Kd>>6;

    auto loadA = [&](int ko, int st) {
        #pragma unroll 4
        for (int u = tid; u < 1024; u += 256) {
            int r = u>>3, c = u&7;
            cpa16(sa + st*AH*2 + (r*72+c*8)*2, A + (long)(m0+r)*lda + ko + c*8);
        }
    };
    auto loadB = [&](int ko, int st) {
        if (BNN) {
            #pragma unroll 4
            for (int u = tid; u < 64*(BN/8); u += 256) {
                int r = u/(BN/8), c = u%(BN/8);
                cpa16(sb + st*BH*2 + (r*136+c*8)*2, Bm + (long)(ko+r)*ldb + n0 + c*8);
            }
        } else {
            #pragma unroll 2
            for (int u = tid; u < BN*8; u += 256) {
                int r = u>>3, c = u&7;
                long rr = GATHER ? (long)sidx[n0+r] : (long)(n0+r);
                cpa16(sb + st*BH*2 + (r*72+c*8)*2, Bm + rr*ldb + ko + c*8);
            }
        }
    };

    // prime stages 0,1
    loadA(0,0); loadB(0,0);
    asm volatile("cp.async.commit_group;");
    if (nch > 1) { loadA(64,1); loadB(64,1); }
    asm volatile("cp.async.commit_group;");

    int st = 0;
    for (int it = 0; it < nch; ++it) {
        asm volatile("cp.async.wait_group 1;");
        __syncthreads();

        const uint32_t sab = sa + st*AH*2;
        const uint32_t sbb = sb + st*BH*2;
        #pragma unroll
        for (int kk = 0; kk < 64; kk += 16) {
            uint32_t af[4][4], bf[NT][2];
            #pragma unroll
            for (int mt = 0; mt < 4; mt++) {
                int r = wm + mt*16 + (lane&15);
                ldsm4(af[mt], sab + (r*72 + kk + (lane>>4)*8)*2);
            }
            if (BNN) {
                #pragma unroll
                for (int np = 0; np < NT/2; np++) {
                    uint32_t b4[4];
                    int r = kk + (lane&15);
                    int co = wn + np*16 + (lane>>4)*8;
                    ldsm4t(b4, sbb + (r*136 + co)*2);
                    bf[2*np][0]   = b4[0]; bf[2*np][1]   = b4[1];
                    bf[2*np+1][0] = b4[2]; bf[2*np+1][1] = b4[3];
                }
            } else {
                #pragma unroll
                for (int nt = 0; nt < NT; nt++) {
                    int r = wn + nt*8 + (lane&7);
                    int co = kk + ((lane>>3)&1)*8;
                    ldsm2(bf[nt], sbb + (r*72 + co)*2);
                }
            }
            #pragma unroll
            for (int mt = 0; mt < 4; mt++)
                #pragma unroll
                for (int nt = 0; nt < NT; nt++)
                    mma16816(acc[mt][nt], af[mt], bf[nt]);
        }
        __syncthreads();
        if (it+2 < nch) {
            loadA((it+2)<<6, (st+2)%NSTG); loadB((it+2)<<6, (st+2)%NSTG);
        }
        asm volatile("cp.async.commit_group;");
        st = (st+1)%NSTG;
    }

    // ---- epilogue ----
    float* Cf = (float*)Cv;
    __half* Cb = (__half*)Cv;
    const long coff = zb*sCb + zh*sCh;
    #pragma unroll
    for (int mt = 0; mt < 4; mt++) {
        #pragma unroll
        for (int hf = 0; hf < 2; hf++) {
            const int gm = m0 + wm + mt*16 + (lane>>2) + hf*8;
            const float xnr = (EPI==3) ? xn[(long)z*M + gm] : 0.f;
            #pragma unroll
            for (int nt = 0; nt < NT; nt++) {
                const int gn = n0 + wn + nt*8 + (lane&3)*2;
                float v0 = acc[mt][nt][hf*2+0];
                float v1 = acc[mt][nt][hf*2+1];
                if (EPI==0) {
                    if (bias) { v0 += bias[gn]; v1 += bias[gn+1]; }
                } else if (EPI==1) {
                    float t0 = v0 + bias[gn];   v0 = t0 * normcdff(t0);
                    float t1 = v1 + bias[gn+1]; v1 = t1 * normcdff(t1);
                } else if (EPI==2) {
                    v0 *= alpha; v1 *= alpha;
                } else if (EPI==3) {
                    v0 = sqrtf(fmaxf(xnr + xn[(long)z*M + sidx[gn]]   - 2.f*v0, 0.f));
                    v1 = sqrtf(fmaxf(xnr + xn[(long)z*M + sidx[gn+1]] - 2.f*v1, 0.f));
                }
                if (PACKOUT) {
                    __half2 hh; hh.x = __float2half_rn(v0); hh.y = __float2half_rn(v1);
                    *(__half2*)(Cb + coff + (long)gm*ldc + gn) = hh;
                } else {
                    float2 st2; st2.x=v0; st2.y=v1;
                    *(float2*)(Cf + coff + (long)gm*ldc + gn) = st2;
                }
            }
        }
    }
}

// ================= fused flash attention =================
__global__ __launch_bounds__(256)
void flash_k(const __half* __restrict__ qkv, __half* __restrict__ opack) {
    extern __shared__ __half fs[];
    constexpr int LD = 72;
    constexpr int TB = 128*LD;
    const int z = blockIdx.y, b = z/H_, h = z - b*H_;
    const int qb = blockIdx.x;
    const int tid = threadIdx.x, warp = tid>>5, lane = tid&31;
    const int g = lane>>2, t = lane&3;
    const int wm = warp*16;

    const __half* qg = qkv + ((long)b*S_ + qb*128)*2304 + h*64;
    const __half* kg = qkv + (long)b*S_*2304 + 768 + h*64;
    const __half* vg = qkv + (long)b*S_*2304 + 1536 + h*64;
    const uint32_t sq = smem_to_u32(fs);
    const uint32_t sk = sq + TB*2;
    const uint32_t sv = sq + 3*TB*2;

    for (int u = tid; u < 1024; u += 256) {
        int r = u>>3, c = u&7;
        cpa16(sq + (r*LD + c*8)*2, qg + (long)r*2304 + c*8);
        cpa16(sk + (r*LD + c*8)*2, kg + (long)r*2304 + c*8);
        cpa16(sv + (r*LD + c*8)*2, vg + (long)r*2304 + c*8);
    }
    asm volatile("cp.async.commit_group;");
    asm volatile("cp.async.wait_group 0;");
    __syncthreads();

    uint32_t qf[4][4];
    #pragma unroll
    for (int kc = 0; kc < 4; kc++) {
        int r = wm + (lane&15);
        ldsm4(qf[kc], sq + (r*LD + kc*16 + (lane>>4)*8)*2);
    }

    float m0 = -1e30f, m1 = -1e30f, l0 = 0.f, l1 = 0.f;
    float oacc[8][4];
    #pragma unroll
    for (int i=0;i<8;i++) { oacc[i][0]=0.f; oacc[i][1]=0.f; oacc[i][2]=0.f; oacc[i][3]=0.f; }

    for (int kb = 0; kb < 4; ++kb) {
        const int buf = kb&1;
        if (kb) {
            asm volatile("cp.async.wait_group 0;");
            __syncthreads();
        }
        if (kb < 3) {
            const __half* kn = kg + (long)(kb+1)*128*2304;
            const __half* vn = vg + (long)(kb+1)*128*2304;
            const uint32_t dk = sk + (buf^1)*TB*2, dv = sv + (buf^1)*TB*2;
            for (int u = tid; u < 1024; u += 256) {
                int r = u>>3, c = u&7;
                cpa16(dk + (r*LD+c*8)*2, kn + (long)r*2304 + c*8);
                cpa16(dv + (r*LD+c*8)*2, vn + (long)r*2304 + c*8);
            }
            asm volatile("cp.async.commit_group;");
        }
        const uint32_t skb = sk + buf*TB*2, svb = sv + buf*TB*2;

        float sacc[16][4];
        #pragma unroll
        for (int i=0;i<16;i++) { sacc[i][0]=0.f; sacc[i][1]=0.f; sacc[i][2]=0.f; sacc[i][3]=0.f; }
        #pragma unroll
        for (int kc = 0; kc < 4; kc++) {
            #pragma unroll
            for (int ntp = 0; ntp < 8; ntp++) {
                uint32_t b4[4];
                int r = ntp*16 + (lane&7) + ((lane>>4)&1)*8;
                int co = kc*16 + ((lane>>3)&1)*8;
                ldsm4(b4, skb + (r*LD + co)*2);
                mma16816(sacc[2*ntp],   qf[kc], b4);
                mma16816(sacc[2*ntp+1], qf[kc], b4+2);
            }
        }
        float mx0 = -1e30f, mx1 = -1e30f;
        #pragma unroll
        for (int nt=0;nt<16;nt++) {
            sacc[nt][0]*=0.125f; sacc[nt][1]*=0.125f; sacc[nt][2]*=0.125f; sacc[nt][3]*=0.125f;
            mx0 = fmaxf(mx0, fmaxf(sacc[nt][0], sacc[nt][1]));
            mx1 = fmaxf(mx1, fmaxf(sacc[nt][2], sacc[nt][3]));
        }
        mx0 = fmaxf(mx0, __shfl_xor_sync(0xffffffffu, mx0, 1));
        mx0 = fmaxf(mx0, __shfl_xor_sync(0xffffffffu, mx0, 2));
        mx1 = fmaxf(mx1, __shfl_xor_sync(0xffffffffu, mx1, 1));
        mx1 = fmaxf(mx1, __shfl_xor_sync(0xffffffffu, mx1, 2));
        const float mn0 = fmaxf(m0, mx0), mn1 = fmaxf(m1, mx1);
        const float c0 = __expf(m0 - mn0), c1 = __expf(m1 - mn1);
        m0 = mn0; m1 = mn1;
        float rs0 = 0.f, rs1 = 0.f;
        uint32_t ph0[16], ph1[16];
        #pragma unroll
        for (int nt=0;nt<16;nt++) {
            float e0 = __expf(sacc[nt][0]-mn0), e1 = __expf(sacc[nt][1]-mn0);
            float e2 = __expf(sacc[nt][2]-mn1), e3 = __expf(sacc[nt][3]-mn1);
            rs0 += e0+e1; rs1 += e2+e3;
            __half2 p0 = __floats2half2_rn(e0,e1); ph0[nt] = *(uint32_t*)&p0;
            __half2 p1 = __floats2half2_rn(e2,e3); ph1[nt] = *(uint32_t*)&p1;
        }
        rs0 += __shfl_xor_sync(0xffffffffu, rs0, 1);
        rs0 += __shfl_xor_sync(0xffffffffu, rs0, 2);
        rs1 += __shfl_xor_sync(0xffffffffu, rs1, 1);
        rs1 += __shfl_xor_sync(0xffffffffu, rs1, 2);
        l0 = l0*c0 + rs0; l1 = l1*c1 + rs1;
        #pragma unroll
        for (int i=0;i<8;i++) { oacc[i][0]*=c0; oacc[i][1]*=c0; oacc[i][2]*=c1; oacc[i][3]*=c1; }

        #pragma unroll
        for (int kc = 0; kc < 8; kc++) {
            uint32_t a[4] = { ph0[2*kc], ph1[2*kc], ph0[2*kc+1], ph1[2*kc+1] };
            #pragma unroll
            for (int ntp = 0; ntp < 4; ntp++) {
                uint32_t b4[4];
                int r = kc*16 + (lane&15);
                int co = ntp*16 + (lane>>4)*8;
                ldsm4t(b4, svb + (r*LD + co)*2);
                mma16816(oacc[2*ntp],   a, b4);
                mma16816(oacc[2*ntp+1], a, b4+2);
            }
        }
        __syncthreads();
    }

    const float i0 = 1.0f/l0, i1 = 1.0f/l1;
    __half* o0 = opack + ((long)b*S_ + qb*128 + wm + g)*768 + h*64;
    __half* o1 = o0 + 8*768;
    #pragma unroll
    for (int nt = 0; nt < 8; nt++) {
        __half2 h0 = __floats2half2_rn(oacc[nt][0]*i0, oacc[nt][1]*i0);
        __half2 h1 = __floats2half2_rn(oacc[nt][2]*i1, oacc[nt][3]*i1);
        *(__half2*)(o0 + nt*8 + 2*t) = h0;
        *(__half2*)(o1 + nt*8 + 2*t) = h1;
    }
}

// ================= pack / transform =================
// fp32 x -> fp16 pack + row sq-norm; block 0 also initializes batch stats
__global__ void xsplit_k(const float* __restrict__ x) {
    __shared__ float red[3];
    long r = blockIdx.x; int t = threadIdx.x;
    if (blockIdx.x == 0 && t < B_) {
        g_sum[t]=0.0; g_sumsq[t]=0.0; g_minb[t]=0x7f7fffffu; g_maxb[t]=0u;
    }
    const float* s = x + r*D_ + t*8;
    float f[8];
    *(float4*)(f)   = *(const float4*)(s);
    *(float4*)(f+4) = *(const float4*)(s+4);
    __half h[8];
    float sq = 0.f;
    #pragma unroll
    for (int u = 0; u < 8; u++) { sq += f[u]*f[u]; h[u] = __float2half_rn(f[u]); }
    *(uint4*)(g_xpack + r*D_ + t*8) = *(uint4*)h;
    #pragma unroll
    for (int o = 16; o; o >>= 1) sq += __shfl_xor_sync(0xffffffffu, sq, o);
    if ((t&31)==0) red[t>>5] = sq;
    __syncthreads();
    if (t==0) g_xnorm[r] = red[0]+red[1]+red[2];
}

__global__ void wconv_all_k(const float* __restrict__ w0, const float* __restrict__ w1,
                            const float* __restrict__ w2, const float* __restrict__ w3) {
    int bid = blockIdx.x;
    const float* W; __half* Wh; long base;
    if (bid < 864)      { W = w0; Wh = g_wqkvh; base = bid; }
    else if (bid < 1152){ W = w1; Wh = g_wouth; base = bid - 864; }
    else if (bid < 1728){ W = w2; Wh = g_wf1h;  base = bid - 1152; }
    else                { W = w3; Wh = g_wf2h;  base = bid - 1728; }
    long i = (base*256 + threadIdx.x)*8;
    float f[8];
    *(float4*)(f)   = *(const float4*)(W+i);
    *(float4*)(f+4) = *(const float4*)(W+i+4);
    __half h[8];
    #pragma unroll
    for (int u = 0; u < 8; u++) h[u] = __float2half_rn(f[u]);
    *(uint4*)(Wh + i) = *(uint4*)h;
}

// ================= misc =================
__device__ __forceinline__ float blockReduceSum256(float v, float* red) {
    #pragma unroll
    for (int o = 16; o; o >>= 1) v += __shfl_xor_sync(0xffffffffu, v, o);
    int w = threadIdx.x>>5, l = threadIdx.x&31;
    if (l==0) red[w] = v;
    __syncthreads();
    float r = (threadIdx.x < 8) ? red[threadIdx.x] : 0.f;
    if (w==0) {
        #pragma unroll
        for (int o = 4; o; o >>= 1) r += __shfl_xor_sync(0xffffffffu, r, o);
        if (l==0) red[0] = r;
    }
    __syncthreads();
    float out = red[0];
    __syncthreads();
    return out;
}

__global__ void topk_stats_k() {
    int warp = threadIdx.x >> 5, lane = threadIdx.x & 31;
    long row = (long)blockIdx.x*8 + warp;
    const float4* p = (const float4*)(g_dist + row*NS_);
    float4 v4 = p[lane];
    float v[4] = {v4.x, v4.y, v4.z, v4.w};
    float lsum=0.f, lsq=0.f, mn0=0.f, mx15=0.f;
    #pragma unroll
    for (int it = 0; it < K_; ++it) {
        float lv = fminf(fminf(v[0],v[1]), fminf(v[2],v[3]));
        float m = lv;
        #pragma unroll
        for (int o = 16; o; o >>= 1) m = fminf(m, __shfl_xor_sync(0xffffffffu, m, o));
        unsigned bal = __ballot_sync(0xffffffffu, lv==m);
        if (lane == __ffs(bal)-1) {
            if      (v[0]==m) v[0]=FLT_MAX;
            else if (v[1]==m) v[1]=FLT_MAX;
            else if (v[2]==m) v[2]=FLT_MAX;
            else              v[3]=FLT_MAX;
        }
        lsum += m; lsq += m*m;
        if (it==0) mn0 = m;
        mx15 = m;
    }
    if (lane==0) {
        int b = (int)(row >> 9);
        atomicAdd(&g_sum[b], (double)lsum);
        atomicAdd(&g_sumsq[b], (double)lsq);
        atomicMin(&g_minb[b], __float_as_uint(mn0));
        atomicMax(&g_maxb[b], __float_as_uint(mx15));
    }
}

__global__ void mlp_topo_k(const float* __restrict__ w1, const float* __restrict__ b1,
                           const float* __restrict__ w2, const float* __restrict__ b2,
                           const float* __restrict__ wd0, const float* __restrict__ bd0,
                           const float* __restrict__ topo_w, const float* __restrict__ topo_b,
                           const float* __restrict__ gate) {
    int b = blockIdx.x, tid = threadIdx.x;
    __shared__ float st[6], h1[192], h2[R_], land[R_];
    if (tid==0) {
        double n = 8192.0, s = g_sum[b], sq = g_sumsq[b];
        double mean = s / n;
        double var = (sq - s*s/n) / (n - 1.0);
        float sd = sqrtf(fmaxf((float)var, 0.f));
        st[0]=(float)mean; st[1]=sd;
        st[2]=__uint_as_float(g_minb[b]); st[3]=__uint_as_float(g_maxb[b]);
        st[4]=(float)mean*0.5f; st[5]=sd*0.5f;
    }
    __syncthreads();
    if (tid < 192) {
        float a = b1[tid];
        #pragma unroll
        for (int i = 0; i < 6; i++) a += st[i]*w1[i*192+tid];
        h1[tid] = fmaxf(a, 0.f);
    }
    __syncthreads();
    if (tid < R_) {
        float a = b2[tid];
        for (int i = 0; i < 192; i++) a += h1[i]*w2[i*R_+tid];
        h2[tid] = a;
    }
    __syncthreads();
    if (tid < R_) {
        float a = bd0[tid];
        #pragma unroll
        for (int i = 0; i < R_; i++) a += h2[i]*wd0[i*R_+tid];
        land[tid] = a;
    }
    __syncthreads();
    float gt = *gate;
    for (int d = tid; d < D_; d += blockDim.x) {
        float a = topo_b[d];
        #pragma unroll
        for (int i = 0; i < R_; i++) a += land[i]*topo_w[i*D_+d];
        g_topo[b*D_+d] = gt*a;
    }
}

template<bool FIRST>
__global__ void ln_k(const float* __restrict__ a, const float* __restrict__ br,
                     const float* __restrict__ gamma, const float* __restrict__ beta,
                     float* __restrict__ out, __half* __restrict__ pack) {
    __shared__ float tv[D_];
    __shared__ float red[8];
    long r = blockIdx.x; int tid = threadIdx.x;
    float loc = 0.f;
    for (int d = tid; d < D_; d += 256) {
        float t = a[r*D_+d] + br[r*D_+d];
        if (FIRST) t += g_topo[(r>>9)*D_ + d];
        tv[d] = t; loc += t;
    }
    float mean = blockReduceSum256(loc, red) * (1.f/D_);
    float lv = 0.f;
    for (int d = tid; d < D_; d += 256) { float c = tv[d]-mean; lv += c*c; }
    float var = blockReduceSum256(lv, red) * (1.f/D_);
    float rs = rsqrtf(var + 1e-5f);
    for (int d = tid; d < D_; d += 256) {
        float o = (tv[d]-mean)*rs*gamma[d] + beta[d];
        out[r*D_+d] = o;
        if (FIRST) pack[r*D_+d] = __float2half_rn(o);
    }
}

// ================= host =================
template<class T> static T* symaddr(const void* sym) {
    void* p = nullptr; cudaGetSymbolAddress(&p, sym); return (T*)p;
}

extern "C" void kernel_launch(void* const* d_in, const int* in_sizes, int n_in,
                              void* d_out, int out_size) {
    const float* x      = (const float*)d_in[0];
    const int*   sidx   = (const int*)  d_in[1];
    const float* w1     = (const float*)d_in[2];
    const float* b1     = (const float*)d_in[3];
    const float* w2     = (const float*)d_in[4];
    const float* b2     = (const float*)d_in[5];
    const float* wd0    = (const float*)d_in[6];
    const float* bd0    = (const float*)d_in[7];
    const float* in_w   = (const float*)d_in[10];
    const float* in_b   = (const float*)d_in[11];
    const float* out_w  = (const float*)d_in[12];
    const float* out_b  = (const float*)d_in[13];
    const float* topo_w = (const float*)d_in[14];
    const float* topo_b = (const float*)d_in[15];
    const float* gate   = (const float*)d_in[16];
    const float* ln1_g  = (const float*)d_in[17];
    const float* ln1_b  = (const float*)d_in[18];
    const float* ln2_g  = (const float*)d_in[19];
    const float* ln2_b  = (const float*)d_in[20];
    const float* ffn_w1 = (const float*)d_in[21];
    const float* ffn_b1 = (const float*)d_in[22];
    const float* ffn_w2 = (const float*)d_in[23];
    const float* ffn_b2 = (const float*)d_in[24];
    float* out = (float*)d_out;

    auto p_xnorm = symaddr<float>(g_xnorm);
    auto p_dist  = symaddr<float>(g_dist);
    auto p_xp    = symaddr<__half>(g_xpack);
    auto p_qkvp  = symaddr<__half>(g_qkvpack);
    auto p_op    = symaddr<__half>(g_opack);
    auto p_attnP = symaddr<float>(g_attnP);
    auto p_x1    = symaddr<float>(g_x1);
    auto p_x1p   = symaddr<__half>(g_x1pack);
    auto p_hp    = symaddr<__half>(g_hpack);
    auto p_ffn2  = symaddr<float>(g_ffn2);
    auto p_wqkv  = symaddr<__half>(g_wqkvh);
    auto p_wout  = symaddr<__half>(g_wouth);
    auto p_wf1   = symaddr<__half>(g_wf1h);
    auto p_wf2   = symaddr<__half>(g_wf2h);

    // dynamic smem sizes: 3 stages of (A:128x72 + B)
    constexpr int SM_BNN = 3*(128*72 + 64*136)*2;   // 105216 (same for BN=128 and BN=64 BNN)
    constexpr int SM_NT  = 3*(128*72 + 64*72)*2;    // 82944
    constexpr int FSMEM  = 5*128*72*2;              // 92160
    cudaFuncSetAttribute(hgemm<128,0,true ,true ,false>, cudaFuncAttributeMaxDynamicSharedMemorySize, SM_BNN);
    cudaFuncSetAttribute(hgemm<64, 0,false,true ,false>, cudaFuncAttributeMaxDynamicSharedMemorySize, SM_BNN);
    cudaFuncSetAttribute(hgemm<128,1,true ,true ,false>, cudaFuncAttributeMaxDynamicSharedMemorySize, SM_BNN);
    cudaFuncSetAttribute(hgemm<64, 3,false,false,true >, cudaFuncAttributeMaxDynamicSharedMemorySize, SM_NT);
    cudaFuncSetAttribute(flash_k, cudaFuncAttributeMaxDynamicSharedMemorySize, FSMEM);

    // prep (init fused into xsplit block 0)
    xsplit_k<<<BS_,96>>>(x);
    wconv_all_k<<<2304,256>>>(in_w, out_w, ffn_w1, ffn_w2);

    // cdist -> dist (NT, gathered B rows)
    hgemm<64,3,false,false,true><<<dim3(2,4,B_),256,SM_NT>>>(
        p_xp, p_xp, p_dist, nullptr,
        S_, D_, D_, D_, NS_,
        1, (long)S_*D_, 0, (long)S_*D_, 0, (long)S_*NS_, 0,
        0.f, p_xnorm, sidx);
    topk_stats_k<<<BS_/8,256>>>();
    mlp_topo_k<<<B_,256>>>(w1,b1,w2,b2,wd0,bd0,topo_w,topo_b,gate);

    // QKV projection (NN, packed fp16 out)
    hgemm<128,0,true,true,false><<<dim3(18,64,1),256,SM_BNN>>>(
        p_xp, p_wqkv, p_qkvp, in_b,
        BS_, D_, D_, 3*D_, 3*D_,
        1, 0,0,0,0,0,0, 0.f, nullptr, nullptr);

    // fused attention
    flash_k<<<dim3(4,Z_),256,FSMEM>>>(p_qkvp, p_op);

    // attn out projection (NN, BN=64 for wave balance)
    hgemm<64,0,false,true,false><<<dim3(12,64,1),256,SM_BNN>>>(
        p_op, p_wout, p_attnP, out_b,
        BS_, D_, D_, D_, D_,
        1, 0,0,0,0,0,0, 0.f, nullptr, nullptr);

    ln_k<true><<<BS_,256>>>(x, p_attnP, ln1_g, ln1_b, p_x1, p_x1p);

    // FFN (NN)
    hgemm<128,1,true,true,false><<<dim3(12,64,1),256,SM_BNN>>>(
        p_x1p, p_wf1, p_hp, ffn_b1,
        BS_, D_, D_, 2*D_, 2*D_,
        1, 0,0,0,0,0,0, 0.f, nullptr, nullptr);
    hgemm<64,0,false,true,false><<<dim3(12,64,1),256,SM_BNN>>>(
        p_hp, p_wf2, p_ffn2, ffn_b2,
        BS_, 2*D_, 2*D_, D_, D_,
        1, 0,0,0,0,0,0, 0.f, nullptr, nullptr);

    ln_k<false><<<BS_,256>>>(p_x1, p_ffn2, ln2_g, ln2_b, out, nullptr);
}

// round 12
// speedup vs baseline: 1.0816x; 1.0816x over previous
#include <cuda_runtime.h>
#include <cuda_fp16.h>
#include <float.h>
#include <cstdint>

#define B_   16
#define S_   512
#define D_   768
#define H_   12
#define HD_  64
#define K_   16
#define NS_  128
#define R_   32
#define BS_  (B_*S_)
#define Z_   (B_*H_)

// ================= PTX helpers =================
__device__ __forceinline__ uint32_t smem_to_u32(const void* p) {
    uint32_t a;
    asm("{ .reg .u64 t; cvta.to.shared.u64 t, %1; cvt.u32.u64 %0, t; }" : "=r"(a) : "l"(p));
    return a;
}
__device__ __forceinline__ void cpa16(uint32_t dst, const void* src) {
    asm volatile("cp.async.ca.shared.global [%0], [%1], 16;" :: "r"(dst), "l"(src));
}
__device__ __forceinline__ void ldsm4(uint32_t* r, uint32_t addr) {
    asm volatile("ldmatrix.sync.aligned.m8n8.x4.shared.b16 {%0,%1,%2,%3}, [%4];"
        : "=r"(r[0]), "=r"(r[1]), "=r"(r[2]), "=r"(r[3]) : "r"(addr));
}
__device__ __forceinline__ void ldsm2(uint32_t* r, uint32_t addr) {
    asm volatile("ldmatrix.sync.aligned.m8n8.x2.shared.b16 {%0,%1}, [%2];"
        : "=r"(r[0]), "=r"(r[1]) : "r"(addr));
}
__device__ __forceinline__ void ldsm4t(uint32_t* r, uint32_t addr) {
    asm volatile("ldmatrix.sync.aligned.m8n8.x4.trans.shared.b16 {%0,%1,%2,%3}, [%4];"
        : "=r"(r[0]), "=r"(r[1]), "=r"(r[2]), "=r"(r[3]) : "r"(addr));
}
__device__ __forceinline__ void mma16816(float* c, const uint32_t* a, const uint32_t* b) {
    asm volatile("mma.sync.aligned.m16n8k16.row.col.f32.f16.f16.f32 "
        "{%0,%1,%2,%3}, {%4,%5,%6,%7}, {%8,%9}, {%0,%1,%2,%3};"
        : "+f"(c[0]), "+f"(c[1]), "+f"(c[2]), "+f"(c[3])
        : "r"(a[0]), "r"(a[1]), "r"(a[2]), "r"(a[3]), "r"(b[0]), "r"(b[1]));
}

// ================= scratch =================
__device__ float    g_xnorm[BS_];
__device__ double   g_sum[B_], g_sumsq[B_];
__device__ unsigned g_minb[B_], g_maxb[B_];
__device__ float    g_dist[B_*S_*NS_];
__device__ float    g_topo[B_*D_];
__device__ __align__(16) __half g_xpack [BS_*D_];
__device__ __align__(16) __half g_qkvpack[(size_t)BS_*3*D_];
__device__ __align__(16) __half g_opack [BS_*D_];
__device__ float    g_attnP[BS_*D_];
__device__ float    g_x1[BS_*D_];
__device__ __align__(16) __half g_x1pack[BS_*D_];
__device__ __align__(16) __half g_hpack [(size_t)BS_*2*D_];
__device__ float    g_ffn2[BS_*D_];
__device__ __align__(16) __half g_wqkvh[D_*3*D_];     // [K][N] fp16
__device__ __align__(16) __half g_wouth[D_*D_];
__device__ __align__(16) __half g_wf1h [D_*2*D_];
__device__ __align__(16) __half g_wf2h [2*D_*D_];

// ================= HMMA GEMM (3-stage pipeline, BK=64) =================
// C[128,BN] = A[M,K] * B.  BNN=true: B stored [K][N]; false: B stored [N][K].
// GATHER (NT only): B row index comes from sidx[n0+r].
// EPI: 0=+bias, 1=gelu, 2=*alpha, 3=cdist.
template<int BN, int EPI, bool PACKOUT, bool BNN, bool GATHER>
__global__ __launch_bounds__(256,2)
void hgemm(const __half* __restrict__ A, const __half* __restrict__ Bm,
           void* __restrict__ Cv, const float* __restrict__ bias,
           int M, int Kd, int lda, int ldb, int ldc,
           int Hdiv, long sAb, long sAh, long sBb, long sBh, long sCb, long sCh,
           float alpha, const float* __restrict__ xn, const int* __restrict__ sidx)
{
    constexpr int NT = BN/32;
    constexpr int NW = BN/4;
    constexpr int AH = 128*72;                 // halfs per A stage (BK=64 + 8 pad)
    constexpr int BH = BNN ? 64*136 : BN*72;   // halfs per B stage
    constexpr int NSTG = 3;
    extern __shared__ __half dsm[];

    const int tid = threadIdx.x, warp = tid>>5, lane = tid&31;
    const int wm = (warp>>2)*64, wn = (warp&3)*NW;
    const int z = blockIdx.z, zb = z/Hdiv, zh = z - zb*Hdiv;
    A  += zb*sAb + zh*sAh;
    Bm += zb*sBb + zh*sBh;
    const int n0 = blockIdx.x*BN, m0 = blockIdx.y*128;
    const uint32_t sa = smem_to_u32(dsm);
    const uint32_t sb = sa + NSTG*AH*2;

    float acc[4][NT][4];
    #pragma unroll
    for (int i=0;i<4;i++)
        #pragma unroll
        for (int j=0;j<NT;j++)
            #pragma unroll
            for (int q=0;q<4;q++) acc[i][j][q]=0.f;

    const int nch = Kd>>6;

    auto loadA = [&](int ko, int st) {
        #pragma unroll 4
        for (int u = tid; u < 1024; u += 256) {
            int r = u>>3, c = u&7;
            cpa16(sa + st*AH*2 + (r*72+c*8)*2, A + (long)(m0+r)*lda + ko + c*8);
        }
    };
    auto loadB = [&](int ko, int st) {
        if (BNN) {
            #pragma unroll 4
            for (int u = tid; u < 64*(BN/8); u += 256) {
                int r = u/(BN/8), c = u%(BN/8);
                cpa16(sb + st*BH*2 + (r*136+c*8)*2, Bm + (long)(ko+r)*ldb + n0 + c*8);
            }
        } else {
            #pragma unroll 2
            for (int u = tid; u < BN*8; u += 256) {
                int r = u>>3, c = u&7;
                long rr = GATHER ? (long)sidx[n0+r] : (long)(n0+r);
                cpa16(sb + st*BH*2 + (r*72+c*8)*2, Bm + rr*ldb + ko + c*8);
            }
        }
    };

    // prime stages 0,1
    loadA(0,0); loadB(0,0);
    asm volatile("cp.async.commit_group;");
    if (nch > 1) { loadA(64,1); loadB(64,1); }
    asm volatile("cp.async.commit_group;");

    int st = 0;
    for (int it = 0; it < nch; ++it) {
        asm volatile("cp.async.wait_group 1;");
        __syncthreads();

        const uint32_t sab = sa + st*AH*2;
        const uint32_t sbb = sb + st*BH*2;
        #pragma unroll
        for (int kk = 0; kk < 64; kk += 16) {
            uint32_t af[4][4], bf[NT][2];
            #pragma unroll
            for (int mt = 0; mt < 4; mt++) {
                int r = wm + mt*16 + (lane&15);
                ldsm4(af[mt], sab + (r*72 + kk + (lane>>4)*8)*2);
            }
            if (BNN) {
                #pragma unroll
                for (int np = 0; np < NT/2; np++) {
                    uint32_t b4[4];
                    int r = kk + (lane&15);
                    int co = wn + np*16 + (lane>>4)*8;
                    ldsm4t(b4, sbb + (r*136 + co)*2);
                    bf[2*np][0]   = b4[0]; bf[2*np][1]   = b4[1];
                    bf[2*np+1][0] = b4[2]; bf[2*np+1][1] = b4[3];
                }
            } else {
                #pragma unroll
                for (int nt = 0; nt < NT; nt++) {
                    int r = wn + nt*8 + (lane&7);
                    int co = kk + ((lane>>3)&1)*8;
                    ldsm2(bf[nt], sbb + (r*72 + co)*2);
                }
            }
            #pragma unroll
            for (int mt = 0; mt < 4; mt++)
                #pragma unroll
                for (int nt = 0; nt < NT; nt++)
                    mma16816(acc[mt][nt], af[mt], bf[nt]);
        }
        __syncthreads();
        if (it+2 < nch) {
            loadA((it+2)<<6, (st+2)%NSTG); loadB((it+2)<<6, (st+2)%NSTG);
        }
        asm volatile("cp.async.commit_group;");
        st = (st+1)%NSTG;
    }

    // ---- epilogue ----
    float* Cf = (float*)Cv;
    __half* Cb = (__half*)Cv;
    const long coff = zb*sCb + zh*sCh;
    #pragma unroll
    for (int mt = 0; mt < 4; mt++) {
        #pragma unroll
        for (int hf = 0; hf < 2; hf++) {
            const int gm = m0 + wm + mt*16 + (lane>>2) + hf*8;
            const float xnr = (EPI==3) ? xn[(long)z*M + gm] : 0.f;
            #pragma unroll
            for (int nt = 0; nt < NT; nt++) {
                const int gn = n0 + wn + nt*8 + (lane&3)*2;
                float v0 = acc[mt][nt][hf*2+0];
                float v1 = acc[mt][nt][hf*2+1];
                if (EPI==0) {
                    if (bias) { v0 += bias[gn]; v1 += bias[gn+1]; }
                } else if (EPI==1) {
                    float t0 = v0 + bias[gn];   v0 = t0 * normcdff(t0);
                    float t1 = v1 + bias[gn+1]; v1 = t1 * normcdff(t1);
                } else if (EPI==2) {
                    v0 *= alpha; v1 *= alpha;
                } else if (EPI==3) {
                    v0 = sqrtf(fmaxf(xnr + xn[(long)z*M + sidx[gn]]   - 2.f*v0, 0.f));
                    v1 = sqrtf(fmaxf(xnr + xn[(long)z*M + sidx[gn+1]] - 2.f*v1, 0.f));
                }
                if (PACKOUT) {
                    __half2 hh; hh.x = __float2half_rn(v0); hh.y = __float2half_rn(v1);
                    *(__half2*)(Cb + coff + (long)gm*ldc + gn) = hh;
                } else {
                    float2 st2; st2.x=v0; st2.y=v1;
                    *(float2*)(Cf + coff + (long)gm*ldc + gn) = st2;
                }
            }
        }
    }
}

// ================= fused flash attention =================
__global__ __launch_bounds__(256)
void flash_k(const __half* __restrict__ qkv, __half* __restrict__ opack) {
    extern __shared__ __half fs[];
    constexpr int LD = 72;
    constexpr int TB = 128*LD;
    const int z = blockIdx.y, b = z/H_, h = z - b*H_;
    const int qb = blockIdx.x;
    const int tid = threadIdx.x, warp = tid>>5, lane = tid&31;
    const int g = lane>>2, t = lane&3;
    const int wm = warp*16;

    const __half* qg = qkv + ((long)b*S_ + qb*128)*2304 + h*64;
    const __half* kg = qkv + (long)b*S_*2304 + 768 + h*64;
    const __half* vg = qkv + (long)b*S_*2304 + 1536 + h*64;
    const uint32_t sq = smem_to_u32(fs);
    const uint32_t sk = sq + TB*2;
    const uint32_t sv = sq + 3*TB*2;

    for (int u = tid; u < 1024; u += 256) {
        int r = u>>3, c = u&7;
        cpa16(sq + (r*LD + c*8)*2, qg + (long)r*2304 + c*8);
        cpa16(sk + (r*LD + c*8)*2, kg + (long)r*2304 + c*8);
        cpa16(sv + (r*LD + c*8)*2, vg + (long)r*2304 + c*8);
    }
    asm volatile("cp.async.commit_group;");
    asm volatile("cp.async.wait_group 0;");
    __syncthreads();

    uint32_t qf[4][4];
    #pragma unroll
    for (int kc = 0; kc < 4; kc++) {
        int r = wm + (lane&15);
        ldsm4(qf[kc], sq + (r*LD + kc*16 + (lane>>4)*8)*2);
    }

    float m0 = -1e30f, m1 = -1e30f, l0 = 0.f, l1 = 0.f;
    float oacc[8][4];
    #pragma unroll
    for (int i=0;i<8;i++) { oacc[i][0]=0.f; oacc[i][1]=0.f; oacc[i][2]=0.f; oacc[i][3]=0.f; }

    for (int kb = 0; kb < 4; ++kb) {
        const int buf = kb&1;
        if (kb) {
            asm volatile("cp.async.wait_group 0;");
            __syncthreads();
        }
        if (kb < 3) {
            const __half* kn = kg + (long)(kb+1)*128*2304;
            const __half* vn = vg + (long)(kb+1)*128*2304;
            const uint32_t dk = sk + (buf^1)*TB*2, dv = sv + (buf^1)*TB*2;
            for (int u = tid; u < 1024; u += 256) {
                int r = u>>3, c = u&7;
                cpa16(dk + (r*LD+c*8)*2, kn + (long)r*2304 + c*8);
                cpa16(dv + (r*LD+c*8)*2, vn + (long)r*2304 + c*8);
            }
            asm volatile("cp.async.commit_group;");
        }
        const uint32_t skb = sk + buf*TB*2, svb = sv + buf*TB*2;

        float sacc[16][4];
        #pragma unroll
        for (int i=0;i<16;i++) { sacc[i][0]=0.f; sacc[i][1]=0.f; sacc[i][2]=0.f; sacc[i][3]=0.f; }
        #pragma unroll
        for (int kc = 0; kc < 4; kc++) {
            #pragma unroll
            for (int ntp = 0; ntp < 8; ntp++) {
                uint32_t b4[4];
                int r = ntp*16 + (lane&7) + ((lane>>4)&1)*8;
                int co = kc*16 + ((lane>>3)&1)*8;
                ldsm4(b4, skb + (r*LD + co)*2);
                mma16816(sacc[2*ntp],   qf[kc], b4);
                mma16816(sacc[2*ntp+1], qf[kc], b4+2);
            }
        }
        float mx0 = -1e30f, mx1 = -1e30f;
        #pragma unroll
        for (int nt=0;nt<16;nt++) {
            sacc[nt][0]*=0.125f; sacc[nt][1]*=0.125f; sacc[nt][2]*=0.125f; sacc[nt][3]*=0.125f;
            mx0 = fmaxf(mx0, fmaxf(sacc[nt][0], sacc[nt][1]));
            mx1 = fmaxf(mx1, fmaxf(sacc[nt][2], sacc[nt][3]));
        }
        mx0 = fmaxf(mx0, __shfl_xor_sync(0xffffffffu, mx0, 1));
        mx0 = fmaxf(mx0, __shfl_xor_sync(0xffffffffu, mx0, 2));
        mx1 = fmaxf(mx1, __shfl_xor_sync(0xffffffffu, mx1, 1));
        mx1 = fmaxf(mx1, __shfl_xor_sync(0xffffffffu, mx1, 2));
        const float mn0 = fmaxf(m0, mx0), mn1 = fmaxf(m1, mx1);
        const float c0 = __expf(m0 - mn0), c1 = __expf(m1 - mn1);
        m0 = mn0; m1 = mn1;
        float rs0 = 0.f, rs1 = 0.f;
        uint32_t ph0[16], ph1[16];
        #pragma unroll
        for (int nt=0;nt<16;nt++) {
            float e0 = __expf(sacc[nt][0]-mn0), e1 = __expf(sacc[nt][1]-mn0);
            float e2 = __expf(sacc[nt][2]-mn1), e3 = __expf(sacc[nt][3]-mn1);
            rs0 += e0+e1; rs1 += e2+e3;
            __half2 p0 = __floats2half2_rn(e0,e1); ph0[nt] = *(uint32_t*)&p0;
            __half2 p1 = __floats2half2_rn(e2,e3); ph1[nt] = *(uint32_t*)&p1;
        }
        rs0 += __shfl_xor_sync(0xffffffffu, rs0, 1);
        rs0 += __shfl_xor_sync(0xffffffffu, rs0, 2);
        rs1 += __shfl_xor_sync(0xffffffffu, rs1, 1);
        rs1 += __shfl_xor_sync(0xffffffffu, rs1, 2);
        l0 = l0*c0 + rs0; l1 = l1*c1 + rs1;
        #pragma unroll
        for (int i=0;i<8;i++) { oacc[i][0]*=c0; oacc[i][1]*=c0; oacc[i][2]*=c1; oacc[i][3]*=c1; }

        #pragma unroll
        for (int kc = 0; kc < 8; kc++) {
            uint32_t a[4] = { ph0[2*kc], ph1[2*kc], ph0[2*kc+1], ph1[2*kc+1] };
            #pragma unroll
            for (int ntp = 0; ntp < 4; ntp++) {
                uint32_t b4[4];
                int r = kc*16 + (lane&15);
                int co = ntp*16 + (lane>>4)*8;
                ldsm4t(b4, svb + (r*LD + co)*2);
                mma16816(oacc[2*ntp],   a, b4);
                mma16816(oacc[2*ntp+1], a, b4+2);
            }
        }
        __syncthreads();
    }

    const float i0 = 1.0f/l0, i1 = 1.0f/l1;
    __half* o0 = opack + ((long)b*S_ + qb*128 + wm + g)*768 + h*64;
    __half* o1 = o0 + 8*768;
    #pragma unroll
    for (int nt = 0; nt < 8; nt++) {
        __half2 h0 = __floats2half2_rn(oacc[nt][0]*i0, oacc[nt][1]*i0);
        __half2 h1 = __floats2half2_rn(oacc[nt][2]*i1, oacc[nt][3]*i1);
        *(__half2*)(o0 + nt*8 + 2*t) = h0;
        *(__half2*)(o1 + nt*8 + 2*t) = h1;
    }
}

// ================= pack / transform =================
// fp32 x -> fp16 pack + row sq-norm; block 0 also initializes batch stats
__global__ void xsplit_k(const float* __restrict__ x) {
    __shared__ float red[3];
    long r = blockIdx.x; int t = threadIdx.x;
    if (blockIdx.x == 0 && t < B_) {
        g_sum[t]=0.0; g_sumsq[t]=0.0; g_minb[t]=0x7f7fffffu; g_maxb[t]=0u;
    }
    const float* s = x + r*D_ + t*8;
    float f[8];
    *(float4*)(f)   = *(const float4*)(s);
    *(float4*)(f+4) = *(const float4*)(s+4);
    __half h[8];
    float sq = 0.f;
    #pragma unroll
    for (int u = 0; u < 8; u++) { sq += f[u]*f[u]; h[u] = __float2half_rn(f[u]); }
    *(uint4*)(g_xpack + r*D_ + t*8) = *(uint4*)h;
    #pragma unroll
    for (int o = 16; o; o >>= 1) sq += __shfl_xor_sync(0xffffffffu, sq, o);
    if ((t&31)==0) red[t>>5] = sq;
    __syncthreads();
    if (t==0) g_xnorm[r] = red[0]+red[1]+red[2];
}

__global__ void wconv_all_k(const float* __restrict__ w0, const float* __restrict__ w1,
                            const float* __restrict__ w2, const float* __restrict__ w3) {
    int bid = blockIdx.x;
    const float* W; __half* Wh; long base;
    if (bid < 864)      { W = w0; Wh = g_wqkvh; base = bid; }
    else if (bid < 1152){ W = w1; Wh = g_wouth; base = bid - 864; }
    else if (bid < 1728){ W = w2; Wh = g_wf1h;  base = bid - 1152; }
    else                { W = w3; Wh = g_wf2h;  base = bid - 1728; }
    long i = (base*256 + threadIdx.x)*8;
    float f[8];
    *(float4*)(f)   = *(const float4*)(W+i);
    *(float4*)(f+4) = *(const float4*)(W+i+4);
    __half h[8];
    #pragma unroll
    for (int u = 0; u < 8; u++) h[u] = __float2half_rn(f[u]);
    *(uint4*)(Wh + i) = *(uint4*)h;
}

// ================= misc =================
__device__ __forceinline__ float blockReduceSum256(float v, float* red) {
    #pragma unroll
    for (int o = 16; o; o >>= 1) v += __shfl_xor_sync(0xffffffffu, v, o);
    int w = threadIdx.x>>5, l = threadIdx.x&31;
    if (l==0) red[w] = v;
    __syncthreads();
    float r = (threadIdx.x < 8) ? red[threadIdx.x] : 0.f;
    if (w==0) {
        #pragma unroll
        for (int o = 4; o; o >>= 1) r += __shfl_xor_sync(0xffffffffu, r, o);
        if (l==0) red[0] = r;
    }
    __syncthreads();
    float out = red[0];
    __syncthreads();
    return out;
}

__global__ void topk_stats_k() {
    int warp = threadIdx.x >> 5, lane = threadIdx.x & 31;
    long row = (long)blockIdx.x*8 + warp;
    const float4* p = (const float4*)(g_dist + row*NS_);
    float4 v4 = p[lane];
    float v[4] = {v4.x, v4.y, v4.z, v4.w};
    float lsum=0.f, lsq=0.f, mn0=0.f, mx15=0.f;
    #pragma unroll
    for (int it = 0; it < K_; ++it) {
        float lv = fminf(fminf(v[0],v[1]), fminf(v[2],v[3]));
        float m = lv;
        #pragma unroll
        for (int o = 16; o; o >>= 1) m = fminf(m, __shfl_xor_sync(0xffffffffu, m, o));
        unsigned bal = __ballot_sync(0xffffffffu, lv==m);
        if (lane == __ffs(bal)-1) {
            if      (v[0]==m) v[0]=FLT_MAX;
            else if (v[1]==m) v[1]=FLT_MAX;
            else if (v[2]==m) v[2]=FLT_MAX;
            else              v[3]=FLT_MAX;
        }
        lsum += m; lsq += m*m;
        if (it==0) mn0 = m;
        mx15 = m;
    }
    if (lane==0) {
        int b = (int)(row >> 9);
        atomicAdd(&g_sum[b], (double)lsum);
        atomicAdd(&g_sumsq[b], (double)lsq);
        atomicMin(&g_minb[b], __float_as_uint(mn0));
        atomicMax(&g_maxb[b], __float_as_uint(mx15));
    }
}

__global__ void mlp_topo_k(const float* __restrict__ w1, const float* __restrict__ b1,
                           const float* __restrict__ w2, const float* __restrict__ b2,
                           const float* __restrict__ wd0, const float* __restrict__ bd0,
                           const float* __restrict__ topo_w, const float* __restrict__ topo_b,
                           const float* __restrict__ gate) {
    int b = blockIdx.x, tid = threadIdx.x;
    __shared__ float st[6], h1[192], h2[R_], land[R_];
    if (tid==0) {
        double n = 8192.0, s = g_sum[b], sq = g_sumsq[b];
        double mean = s / n;
        double var = (sq - s*s/n) / (n - 1.0);
        float sd = sqrtf(fmaxf((float)var, 0.f));
        st[0]=(float)mean; st[1]=sd;
        st[2]=__uint_as_float(g_minb[b]); st[3]=__uint_as_float(g_maxb[b]);
        st[4]=(float)mean*0.5f; st[5]=sd*0.5f;
    }
    __syncthreads();
    if (tid < 192) {
        float a = b1[tid];
        #pragma unroll
        for (int i = 0; i < 6; i++) a += st[i]*w1[i*192+tid];
        h1[tid] = fmaxf(a, 0.f);
    }
    __syncthreads();
    if (tid < R_) {
        float a = b2[tid];
        for (int i = 0; i < 192; i++) a += h1[i]*w2[i*R_+tid];
        h2[tid] = a;
    }
    __syncthreads();
    if (tid < R_) {
        float a = bd0[tid];
        #pragma unroll
        for (int i = 0; i < R_; i++) a += h2[i]*wd0[i*R_+tid];
        land[tid] = a;
    }
    __syncthreads();
    float gt = *gate;
    for (int d = tid; d < D_; d += blockDim.x) {
        float a = topo_b[d];
        #pragma unroll
        for (int i = 0; i < R_; i++) a += land[i]*topo_w[i*D_+d];
        g_topo[b*D_+d] = gt*a;
    }
}

template<bool FIRST>
__global__ void ln_k(const float* __restrict__ a, const float* __restrict__ br,
                     const float* __restrict__ gamma, const float* __restrict__ beta,
                     float* __restrict__ out, __half* __restrict__ pack) {
    __shared__ float tv[D_];
    __shared__ float red[8];
    long r = blockIdx.x; int tid = threadIdx.x;
    float loc = 0.f;
    for (int d = tid; d < D_; d += 256) {
        float t = a[r*D_+d] + br[r*D_+d];
        if (FIRST) t += g_topo[(r>>9)*D_ + d];
        tv[d] = t; loc += t;
    }
    float mean = blockReduceSum256(loc, red) * (1.f/D_);
    float lv = 0.f;
    for (int d = tid; d < D_; d += 256) { float c = tv[d]-mean; lv += c*c; }
    float var = blockReduceSum256(lv, red) * (1.f/D_);
    float rs = rsqrtf(var + 1e-5f);
    for (int d = tid; d < D_; d += 256) {
        float o = (tv[d]-mean)*rs*gamma[d] + beta[d];
        out[r*D_+d] = o;
        if (FIRST) pack[r*D_+d] = __float2half_rn(o);
    }
}

// ================= host =================
template<class T> static T* symaddr(const void* sym) {
    void* p = nullptr; cudaGetSymbolAddress(&p, sym); return (T*)p;
}

extern "C" void kernel_launch(void* const* d_in, const int* in_sizes, int n_in,
                              void* d_out, int out_size) {
    const float* x      = (const float*)d_in[0];
    const int*   sidx   = (const int*)  d_in[1];
    const float* w1     = (const float*)d_in[2];
    const float* b1     = (const float*)d_in[3];
    const float* w2     = (const float*)d_in[4];
    const float* b2     = (const float*)d_in[5];
    const float* wd0    = (const float*)d_in[6];
    const float* bd0    = (const float*)d_in[7];
    const float* in_w   = (const float*)d_in[10];
    const float* in_b   = (const float*)d_in[11];
    const float* out_w  = (const float*)d_in[12];
    const float* out_b  = (const float*)d_in[13];
    const float* topo_w = (const float*)d_in[14];
    const float* topo_b = (const float*)d_in[15];
    const float* gate   = (const float*)d_in[16];
    const float* ln1_g  = (const float*)d_in[17];
    const float* ln1_b  = (const float*)d_in[18];
    const float* ln2_g  = (const float*)d_in[19];
    const float* ln2_b  = (const float*)d_in[20];
    const float* ffn_w1 = (const float*)d_in[21];
    const float* ffn_b1 = (const float*)d_in[22];
    const float* ffn_w2 = (const float*)d_in[23];
    const float* ffn_b2 = (const float*)d_in[24];
    float* out = (float*)d_out;

    auto p_xnorm = symaddr<float>(g_xnorm);
    auto p_dist  = symaddr<float>(g_dist);
    auto p_xp    = symaddr<__half>(g_xpack);
    auto p_qkvp  = symaddr<__half>(g_qkvpack);
    auto p_op    = symaddr<__half>(g_opack);
    auto p_attnP = symaddr<float>(g_attnP);
    auto p_x1    = symaddr<float>(g_x1);
    auto p_x1p   = symaddr<__half>(g_x1pack);
    auto p_hp    = symaddr<__half>(g_hpack);
    auto p_ffn2  = symaddr<float>(g_ffn2);
    auto p_wqkv  = symaddr<__half>(g_wqkvh);
    auto p_wout  = symaddr<__half>(g_wouth);
    auto p_wf1   = symaddr<__half>(g_wf1h);
    auto p_wf2   = symaddr<__half>(g_wf2h);

    // dynamic smem sizes: 3 stages of (A:128x72 + B)
    constexpr int SM_BNN = 3*(128*72 + 64*136)*2;   // 105216
    constexpr int SM_NT  = 3*(128*72 + 64*72)*2;    // 82944
    constexpr int FSMEM  = 5*128*72*2;              // 92160
    cudaFuncSetAttribute(hgemm<128,0,true ,true ,false>, cudaFuncAttributeMaxDynamicSharedMemorySize, SM_BNN);
    cudaFuncSetAttribute(hgemm<128,0,false,true ,false>, cudaFuncAttributeMaxDynamicSharedMemorySize, SM_BNN);
    cudaFuncSetAttribute(hgemm<128,1,true ,true ,false>, cudaFuncAttributeMaxDynamicSharedMemorySize, SM_BNN);
    cudaFuncSetAttribute(hgemm<64, 3,false,false,true >, cudaFuncAttributeMaxDynamicSharedMemorySize, SM_NT);
    cudaFuncSetAttribute(flash_k, cudaFuncAttributeMaxDynamicSharedMemorySize, FSMEM);

    // prep (init fused into xsplit block 0)
    xsplit_k<<<BS_,96>>>(x);
    wconv_all_k<<<2304,256>>>(in_w, out_w, ffn_w1, ffn_w2);

    // cdist -> dist (NT, gathered B rows)
    hgemm<64,3,false,false,true><<<dim3(2,4,B_),256,SM_NT>>>(
        p_xp, p_xp, p_dist, nullptr,
        S_, D_, D_, D_, NS_,
        1, (long)S_*D_, 0, (long)S_*D_, 0, (long)S_*NS_, 0,
        0.f, p_xnorm, sidx);
    topk_stats_k<<<BS_/8,256>>>();
    mlp_topo_k<<<B_,256>>>(w1,b1,w2,b2,wd0,bd0,topo_w,topo_b,gate);

    // QKV projection (NN, packed fp16 out)
    hgemm<128,0,true,true,false><<<dim3(18,64,1),256,SM_BNN>>>(
        p_xp, p_wqkv, p_qkvp, in_b,
        BS_, D_, D_, 3*D_, 3*D_,
        1, 0,0,0,0,0,0, 0.f, nullptr, nullptr);

    // fused attention
    flash_k<<<dim3(4,Z_),256,FSMEM>>>(p_qkvp, p_op);

    // attn out projection (NN, BN=128)
    hgemm<128,0,false,true,false><<<dim3(6,64,1),256,SM_BNN>>>(
        p_op, p_wout, p_attnP, out_b,
        BS_, D_, D_, D_, D_,
        1, 0,0,0,0,0,0, 0.f, nullptr, nullptr);

    ln_k<true><<<BS_,256>>>(x, p_attnP, ln1_g, ln1_b, p_x1, p_x1p);

    // FFN (NN)
    hgemm<128,1,true,true,false><<<dim3(12,64,1),256,SM_BNN>>>(
        p_x1p, p_wf1, p_hp, ffn_b1,
        BS_, D_, D_, 2*D_, 2*D_,
        1, 0,0,0,0,0,0, 0.f, nullptr, nullptr);
    hgemm<128,0,false,true,false><<<dim3(6,64,1),256,SM_BNN>>>(
        p_hp, p_wf2, p_ffn2, ffn_b2,
        BS_, 2*D_, 2*D_, D_, D_,
        1, 0,0,0,0,0,0, 0.f, nullptr, nullptr);

    ln_k<false><<<BS_,256>>>(p_x1, p_ffn2, ln2_g, ln2_b, out, nullptr);
}

// round 13
// speedup vs baseline: 1.1563x; 1.0691x over previous
#include <cuda_runtime.h>
#include <cuda_fp16.h>
#include <float.h>
#include <cstdint>

#define B_   16
#define S_   512
#define D_   768
#define H_   12
#define HD_  64
#define K_   16
#define NS_  128
#define R_   32
#define BS_  (B_*S_)
#define Z_   (B_*H_)

// ================= PTX helpers =================
__device__ __forceinline__ uint32_t smem_to_u32(const void* p) {
    uint32_t a;
    asm("{ .reg .u64 t; cvta.to.shared.u64 t, %1; cvt.u32.u64 %0, t; }" : "=r"(a) : "l"(p));
    return a;
}
__device__ __forceinline__ void cpa16(uint32_t dst, const void* src) {
    asm volatile("cp.async.ca.shared.global [%0], [%1], 16;" :: "r"(dst), "l"(src));
}
__device__ __forceinline__ void ldsm4(uint32_t* r, uint32_t addr) {
    asm volatile("ldmatrix.sync.aligned.m8n8.x4.shared.b16 {%0,%1,%2,%3}, [%4];"
        : "=r"(r[0]), "=r"(r[1]), "=r"(r[2]), "=r"(r[3]) : "r"(addr));
}
__device__ __forceinline__ void ldsm2(uint32_t* r, uint32_t addr) {
    asm volatile("ldmatrix.sync.aligned.m8n8.x2.shared.b16 {%0,%1}, [%2];"
        : "=r"(r[0]), "=r"(r[1]) : "r"(addr));
}
__device__ __forceinline__ void ldsm4t(uint32_t* r, uint32_t addr) {
    asm volatile("ldmatrix.sync.aligned.m8n8.x4.trans.shared.b16 {%0,%1,%2,%3}, [%4];"
        : "=r"(r[0]), "=r"(r[1]), "=r"(r[2]), "=r"(r[3]) : "r"(addr));
}
__device__ __forceinline__ void mma16816(float* c, const uint32_t* a, const uint32_t* b) {
    asm volatile("mma.sync.aligned.m16n8k16.row.col.f32.f16.f16.f32 "
        "{%0,%1,%2,%3}, {%4,%5,%6,%7}, {%8,%9}, {%0,%1,%2,%3};"
        : "+f"(c[0]), "+f"(c[1]), "+f"(c[2]), "+f"(c[3])
        : "r"(a[0]), "r"(a[1]), "r"(a[2]), "r"(a[3]), "r"(b[0]), "r"(b[1]));
}

// ================= scratch =================
__device__ float    g_xnorm[BS_];
__device__ double   g_sum[B_], g_sumsq[B_];
__device__ unsigned g_minb[B_], g_maxb[B_];
__device__ float    g_dist[B_*S_*NS_];
__device__ float    g_topo[B_*D_];
__device__ __align__(16) __half g_xpack [BS_*D_];
__device__ __align__(16) __half g_qkvpack[(size_t)BS_*3*D_];
__device__ __align__(16) __half g_opack [BS_*D_];
__device__ float    g_attnP[BS_*D_];
__device__ float    g_x1[BS_*D_];
__device__ __align__(16) __half g_x1pack[BS_*D_];
__device__ __align__(16) __half g_hpack [(size_t)BS_*2*D_];
__device__ float    g_ffn2[BS_*D_];
__device__ __align__(16) __half g_wqkvh[D_*3*D_];     // [K][N] fp16
__device__ __align__(16) __half g_wouth[D_*D_];
__device__ __align__(16) __half g_wf1h [D_*2*D_];
__device__ __align__(16) __half g_wf2h [2*D_*D_];

// ================= HMMA GEMM (3-stage pipeline, BK=64) =================
template<int BN, int EPI, bool PACKOUT, bool BNN, bool GATHER>
__global__ __launch_bounds__(256,2)
void hgemm(const __half* __restrict__ A, const __half* __restrict__ Bm,
           void* __restrict__ Cv, const float* __restrict__ bias,
           int M, int Kd, int lda, int ldb, int ldc,
           int Hdiv, long sAb, long sAh, long sBb, long sBh, long sCb, long sCh,
           float alpha, const float* __restrict__ xn, const int* __restrict__ sidx)
{
    constexpr int NT = BN/32;
    constexpr int NW = BN/4;
    constexpr int AH = 128*72;
    constexpr int BH = BNN ? 64*136 : BN*72;
    constexpr int NSTG = 3;
    extern __shared__ __half dsm[];

    const int tid = threadIdx.x, warp = tid>>5, lane = tid&31;
    const int wm = (warp>>2)*64, wn = (warp&3)*NW;
    const int z = blockIdx.z, zb = z/Hdiv, zh = z - zb*Hdiv;
    A  += zb*sAb + zh*sAh;
    Bm += zb*sBb + zh*sBh;
    const int n0 = blockIdx.x*BN, m0 = blockIdx.y*128;
    const uint32_t sa = smem_to_u32(dsm);
    const uint32_t sb = sa + NSTG*AH*2;

    float acc[4][NT][4];
    #pragma unroll
    for (int i=0;i<4;i++)
        #pragma unroll
        for (int j=0;j<NT;j++)
            #pragma unroll
            for (int q=0;q<4;q++) acc[i][j][q]=0.f;

    const int nch = Kd>>6;

    auto loadA = [&](int ko, int st) {
        #pragma unroll 4
        for (int u = tid; u < 1024; u += 256) {
            int r = u>>3, c = u&7;
            cpa16(sa + st*AH*2 + (r*72+c*8)*2, A + (long)(m0+r)*lda + ko + c*8);
        }
    };
    auto loadB = [&](int ko, int st) {
        if (BNN) {
            #pragma unroll 4
            for (int u = tid; u < 64*(BN/8); u += 256) {
                int r = u/(BN/8), c = u%(BN/8);
                cpa16(sb + st*BH*2 + (r*136+c*8)*2, Bm + (long)(ko+r)*ldb + n0 + c*8);
            }
        } else {
            #pragma unroll 2
            for (int u = tid; u < BN*8; u += 256) {
                int r = u>>3, c = u&7;
                long rr = GATHER ? (long)sidx[n0+r] : (long)(n0+r);
                cpa16(sb + st*BH*2 + (r*72+c*8)*2, Bm + rr*ldb + ko + c*8);
            }
        }
    };

    loadA(0,0); loadB(0,0);
    asm volatile("cp.async.commit_group;");
    if (nch > 1) { loadA(64,1); loadB(64,1); }
    asm volatile("cp.async.commit_group;");

    int st = 0;
    for (int it = 0; it < nch; ++it) {
        asm volatile("cp.async.wait_group 1;");
        __syncthreads();

        const uint32_t sab = sa + st*AH*2;
        const uint32_t sbb = sb + st*BH*2;
        #pragma unroll
        for (int kk = 0; kk < 64; kk += 16) {
            uint32_t af[4][4], bf[NT][2];
            #pragma unroll
            for (int mt = 0; mt < 4; mt++) {
                int r = wm + mt*16 + (lane&15);
                ldsm4(af[mt], sab + (r*72 + kk + (lane>>4)*8)*2);
            }
            if (BNN) {
                #pragma unroll
                for (int np = 0; np < NT/2; np++) {
                    uint32_t b4[4];
                    int r = kk + (lane&15);
                    int co = wn + np*16 + (lane>>4)*8;
                    ldsm4t(b4, sbb + (r*136 + co)*2);
                    bf[2*np][0]   = b4[0]; bf[2*np][1]   = b4[1];
                    bf[2*np+1][0] = b4[2]; bf[2*np+1][1] = b4[3];
                }
            } else {
                #pragma unroll
                for (int nt = 0; nt < NT; nt++) {
                    int r = wn + nt*8 + (lane&7);
                    int co = kk + ((lane>>3)&1)*8;
                    ldsm2(bf[nt], sbb + (r*72 + co)*2);
                }
            }
            #pragma unroll
            for (int mt = 0; mt < 4; mt++)
                #pragma unroll
                for (int nt = 0; nt < NT; nt++)
                    mma16816(acc[mt][nt], af[mt], bf[nt]);
        }
        __syncthreads();
        if (it+2 < nch) {
            loadA((it+2)<<6, (st+2)%NSTG); loadB((it+2)<<6, (st+2)%NSTG);
        }
        asm volatile("cp.async.commit_group;");
        st = (st+1)%NSTG;
    }

    float* Cf = (float*)Cv;
    __half* Cb = (__half*)Cv;
    const long coff = zb*sCb + zh*sCh;
    #pragma unroll
    for (int mt = 0; mt < 4; mt++) {
        #pragma unroll
        for (int hf = 0; hf < 2; hf++) {
            const int gm = m0 + wm + mt*16 + (lane>>2) + hf*8;
            const float xnr = (EPI==3) ? xn[(long)z*M + gm] : 0.f;
            #pragma unroll
            for (int nt = 0; nt < NT; nt++) {
                const int gn = n0 + wn + nt*8 + (lane&3)*2;
                float v0 = acc[mt][nt][hf*2+0];
                float v1 = acc[mt][nt][hf*2+1];
                if (EPI==0) {
                    if (bias) { v0 += bias[gn]; v1 += bias[gn+1]; }
                } else if (EPI==1) {
                    float t0 = v0 + bias[gn];   v0 = t0 * normcdff(t0);
                    float t1 = v1 + bias[gn+1]; v1 = t1 * normcdff(t1);
                } else if (EPI==2) {
                    v0 *= alpha; v1 *= alpha;
                } else if (EPI==3) {
                    v0 = sqrtf(fmaxf(xnr + xn[(long)z*M + sidx[gn]]   - 2.f*v0, 0.f));
                    v1 = sqrtf(fmaxf(xnr + xn[(long)z*M + sidx[gn+1]] - 2.f*v1, 0.f));
                }
                if (PACKOUT) {
                    __half2 hh; hh.x = __float2half_rn(v0); hh.y = __float2half_rn(v1);
                    *(__half2*)(Cb + coff + (long)gm*ldc + gn) = hh;
                } else {
                    float2 st2; st2.x=v0; st2.y=v1;
                    *(float2*)(Cf + coff + (long)gm*ldc + gn) = st2;
                }
            }
        }
    }
}

// ================= fused flash attention =================
__global__ __launch_bounds__(256)
void flash_k(const __half* __restrict__ qkv, __half* __restrict__ opack) {
    extern __shared__ __half fs[];
    constexpr int LD = 72;
    constexpr int TB = 128*LD;
    const int z = blockIdx.y, b = z/H_, h = z - b*H_;
    const int qb = blockIdx.x;
    const int tid = threadIdx.x, warp = tid>>5, lane = tid&31;
    const int g = lane>>2, t = lane&3;
    const int wm = warp*16;

    const __half* qg = qkv + ((long)b*S_ + qb*128)*2304 + h*64;
    const __half* kg = qkv + (long)b*S_*2304 + 768 + h*64;
    const __half* vg = qkv + (long)b*S_*2304 + 1536 + h*64;
    const uint32_t sq = smem_to_u32(fs);
    const uint32_t sk = sq + TB*2;
    const uint32_t sv = sq + 3*TB*2;

    for (int u = tid; u < 1024; u += 256) {
        int r = u>>3, c = u&7;
        cpa16(sq + (r*LD + c*8)*2, qg + (long)r*2304 + c*8);
        cpa16(sk + (r*LD + c*8)*2, kg + (long)r*2304 + c*8);
        cpa16(sv + (r*LD + c*8)*2, vg + (long)r*2304 + c*8);
    }
    asm volatile("cp.async.commit_group;");
    asm volatile("cp.async.wait_group 0;");
    __syncthreads();

    uint32_t qf[4][4];
    #pragma unroll
    for (int kc = 0; kc < 4; kc++) {
        int r = wm + (lane&15);
        ldsm4(qf[kc], sq + (r*LD + kc*16 + (lane>>4)*8)*2);
    }

    float m0 = -1e30f, m1 = -1e30f, l0 = 0.f, l1 = 0.f;
    float oacc[8][4];
    #pragma unroll
    for (int i=0;i<8;i++) { oacc[i][0]=0.f; oacc[i][1]=0.f; oacc[i][2]=0.f; oacc[i][3]=0.f; }

    for (int kb = 0; kb < 4; ++kb) {
        const int buf = kb&1;
        if (kb) {
            asm volatile("cp.async.wait_group 0;");
            __syncthreads();
        }
        if (kb < 3) {
            const __half* kn = kg + (long)(kb+1)*128*2304;
            const __half* vn = vg + (long)(kb+1)*128*2304;
            const uint32_t dk = sk + (buf^1)*TB*2, dv = sv + (buf^1)*TB*2;
            for (int u = tid; u < 1024; u += 256) {
                int r = u>>3, c = u&7;
                cpa16(dk + (r*LD+c*8)*2, kn + (long)r*2304 + c*8);
                cpa16(dv + (r*LD+c*8)*2, vn + (long)r*2304 + c*8);
            }
            asm volatile("cp.async.commit_group;");
        }
        const uint32_t skb = sk + buf*TB*2, svb = sv + buf*TB*2;

        float sacc[16][4];
        #pragma unroll
        for (int i=0;i<16;i++) { sacc[i][0]=0.f; sacc[i][1]=0.f; sacc[i][2]=0.f; sacc[i][3]=0.f; }
        #pragma unroll
        for (int kc = 0; kc < 4; kc++) {
            #pragma unroll
            for (int ntp = 0; ntp < 8; ntp++) {
                uint32_t b4[4];
                int r = ntp*16 + (lane&7) + ((lane>>4)&1)*8;
                int co = kc*16 + ((lane>>3)&1)*8;
                ldsm4(b4, skb + (r*LD + co)*2);
                mma16816(sacc[2*ntp],   qf[kc], b4);
                mma16816(sacc[2*ntp+1], qf[kc], b4+2);
            }
        }
        float mx0 = -1e30f, mx1 = -1e30f;
        #pragma unroll
        for (int nt=0;nt<16;nt++) {
            sacc[nt][0]*=0.125f; sacc[nt][1]*=0.125f; sacc[nt][2]*=0.125f; sacc[nt][3]*=0.125f;
            mx0 = fmaxf(mx0, fmaxf(sacc[nt][0], sacc[nt][1]));
            mx1 = fmaxf(mx1, fmaxf(sacc[nt][2], sacc[nt][3]));
        }
        mx0 = fmaxf(mx0, __shfl_xor_sync(0xffffffffu, mx0, 1));
        mx0 = fmaxf(mx0, __shfl_xor_sync(0xffffffffu, mx0, 2));
        mx1 = fmaxf(mx1, __shfl_xor_sync(0xffffffffu, mx1, 1));
        mx1 = fmaxf(mx1, __shfl_xor_sync(0xffffffffu, mx1, 2));
        const float mn0 = fmaxf(m0, mx0), mn1 = fmaxf(m1, mx1);
        const float c0 = __expf(m0 - mn0), c1 = __expf(m1 - mn1);
        m0 = mn0; m1 = mn1;
        float rs0 = 0.f, rs1 = 0.f;
        uint32_t ph0[16], ph1[16];
        #pragma unroll
        for (int nt=0;nt<16;nt++) {
            float e0 = __expf(sacc[nt][0]-mn0), e1 = __expf(sacc[nt][1]-mn0);
            float e2 = __expf(sacc[nt][2]-mn1), e3 = __expf(sacc[nt][3]-mn1);
            rs0 += e0+e1; rs1 += e2+e3;
            __half2 p0 = __floats2half2_rn(e0,e1); ph0[nt] = *(uint32_t*)&p0;
            __half2 p1 = __floats2half2_rn(e2,e3); ph1[nt] = *(uint32_t*)&p1;
        }
        rs0 += __shfl_xor_sync(0xffffffffu, rs0, 1);
        rs0 += __shfl_xor_sync(0xffffffffu, rs0, 2);
        rs1 += __shfl_xor_sync(0xffffffffu, rs1, 1);
        rs1 += __shfl_xor_sync(0xffffffffu, rs1, 2);
        l0 = l0*c0 + rs0; l1 = l1*c1 + rs1;
        #pragma unroll
        for (int i=0;i<8;i++) { oacc[i][0]*=c0; oacc[i][1]*=c0; oacc[i][2]*=c1; oacc[i][3]*=c1; }

        #pragma unroll
        for (int kc = 0; kc < 8; kc++) {
            uint32_t a[4] = { ph0[2*kc], ph1[2*kc], ph0[2*kc+1], ph1[2*kc+1] };
            #pragma unroll
            for (int ntp = 0; ntp < 4; ntp++) {
                uint32_t b4[4];
                int r = kc*16 + (lane&15);
                int co = ntp*16 + (lane>>4)*8;
                ldsm4t(b4, svb + (r*LD + co)*2);
                mma16816(oacc[2*ntp],   a, b4);
                mma16816(oacc[2*ntp+1], a, b4+2);
            }
        }
        __syncthreads();
    }

    const float i0 = 1.0f/l0, i1 = 1.0f/l1;
    __half* o0 = opack + ((long)b*S_ + qb*128 + wm + g)*768 + h*64;
    __half* o1 = o0 + 8*768;
    #pragma unroll
    for (int nt = 0; nt < 8; nt++) {
        __half2 h0 = __floats2half2_rn(oacc[nt][0]*i0, oacc[nt][1]*i0);
        __half2 h1 = __floats2half2_rn(oacc[nt][2]*i1, oacc[nt][3]*i1);
        *(__half2*)(o0 + nt*8 + 2*t) = h0;
        *(__half2*)(o1 + nt*8 + 2*t) = h1;
    }
}

// ================= pack / transform =================
__global__ void xsplit_k(const float* __restrict__ x) {
    __shared__ float red[3];
    long r = blockIdx.x; int t = threadIdx.x;
    if (blockIdx.x == 0 && t < B_) {
        g_sum[t]=0.0; g_sumsq[t]=0.0; g_minb[t]=0x7f7fffffu; g_maxb[t]=0u;
    }
    const float* s = x + r*D_ + t*8;
    float f[8];
    *(float4*)(f)   = *(const float4*)(s);
    *(float4*)(f+4) = *(const float4*)(s+4);
    __half h[8];
    float sq = 0.f;
    #pragma unroll
    for (int u = 0; u < 8; u++) { sq += f[u]*f[u]; h[u] = __float2half_rn(f[u]); }
    *(uint4*)(g_xpack + r*D_ + t*8) = *(uint4*)h;
    #pragma unroll
    for (int o = 16; o; o >>= 1) sq += __shfl_xor_sync(0xffffffffu, sq, o);
    if ((t&31)==0) red[t>>5] = sq;
    __syncthreads();
    if (t==0) g_xnorm[r] = red[0]+red[1]+red[2];
}

__global__ void wconv_all_k(const float* __restrict__ w0, const float* __restrict__ w1,
                            const float* __restrict__ w2, const float* __restrict__ w3) {
    int bid = blockIdx.x;
    const float* W; __half* Wh; long base;
    if (bid < 864)      { W = w0; Wh = g_wqkvh; base = bid; }
    else if (bid < 1152){ W = w1; Wh = g_wouth; base = bid - 864; }
    else if (bid < 1728){ W = w2; Wh = g_wf1h;  base = bid - 1152; }
    else                { W = w3; Wh = g_wf2h;  base = bid - 1728; }
    long i = (base*256 + threadIdx.x)*8;
    float f[8];
    *(float4*)(f)   = *(const float4*)(W+i);
    *(float4*)(f+4) = *(const float4*)(W+i+4);
    __half h[8];
    #pragma unroll
    for (int u = 0; u < 8; u++) h[u] = __float2half_rn(f[u]);
    *(uint4*)(Wh + i) = *(uint4*)h;
}

// ================= misc =================
__device__ __forceinline__ float blockReduceSum256(float v, float* red) {
    #pragma unroll
    for (int o = 16; o; o >>= 1) v += __shfl_xor_sync(0xffffffffu, v, o);
    int w = threadIdx.x>>5, l = threadIdx.x&31;
    if (l==0) red[w] = v;
    __syncthreads();
    float r = (threadIdx.x < 8) ? red[threadIdx.x] : 0.f;
    if (w==0) {
        #pragma unroll
        for (int o = 4; o; o >>= 1) r += __shfl_xor_sync(0xffffffffu, r, o);
        if (l==0) red[0] = r;
    }
    __syncthreads();
    float out = red[0];
    __syncthreads();
    return out;
}

__global__ void topk_stats_k() {
    int warp = threadIdx.x >> 5, lane = threadIdx.x & 31;
    long row = (long)blockIdx.x*8 + warp;
    const float4* p = (const float4*)(g_dist + row*NS_);
    float4 v4 = p[lane];
    float v[4] = {v4.x, v4.y, v4.z, v4.w};
    float lsum=0.f, lsq=0.f, mn0=0.f, mx15=0.f;
    #pragma unroll
    for (int it = 0; it < K_; ++it) {
        float lv = fminf(fminf(v[0],v[1]), fminf(v[2],v[3]));
        float m = lv;
        #pragma unroll
        for (int o = 16; o; o >>= 1) m = fminf(m, __shfl_xor_sync(0xffffffffu, m, o));
        unsigned bal = __ballot_sync(0xffffffffu, lv==m);
        if (lane == __ffs(bal)-1) {
            if      (v[0]==m) v[0]=FLT_MAX;
            else if (v[1]==m) v[1]=FLT_MAX;
            else if (v[2]==m) v[2]=FLT_MAX;
            else              v[3]=FLT_MAX;
        }
        lsum += m; lsq += m*m;
        if (it==0) mn0 = m;
        mx15 = m;
    }
    if (lane==0) {
        int b = (int)(row >> 9);
        atomicAdd(&g_sum[b], (double)lsum);
        atomicAdd(&g_sumsq[b], (double)lsq);
        atomicMin(&g_minb[b], __float_as_uint(mn0));
        atomicMax(&g_maxb[b], __float_as_uint(mx15));
    }
}

__global__ void mlp_topo_k(const float* __restrict__ w1, const float* __restrict__ b1,
                           const float* __restrict__ w2, const float* __restrict__ b2,
                           const float* __restrict__ wd0, const float* __restrict__ bd0,
                           const float* __restrict__ topo_w, const float* __restrict__ topo_b,
                           const float* __restrict__ gate) {
    int b = blockIdx.x, tid = threadIdx.x;
    __shared__ float st[6], h1[192], h2[R_], land[R_];
    if (tid==0) {
        double n = 8192.0, s = g_sum[b], sq = g_sumsq[b];
        double mean = s / n;
        double var = (sq - s*s/n) / (n - 1.0);
        float sd = sqrtf(fmaxf((float)var, 0.f));
        st[0]=(float)mean; st[1]=sd;
        st[2]=__uint_as_float(g_minb[b]); st[3]=__uint_as_float(g_maxb[b]);
        st[4]=(float)mean*0.5f; st[5]=sd*0.5f;
    }
    __syncthreads();
    if (tid < 192) {
        float a = b1[tid];
        #pragma unroll
        for (int i = 0; i < 6; i++) a += st[i]*w1[i*192+tid];
        h1[tid] = fmaxf(a, 0.f);
    }
    __syncthreads();
    if (tid < R_) {
        float a = b2[tid];
        for (int i = 0; i < 192; i++) a += h1[i]*w2[i*R_+tid];
        h2[tid] = a;
    }
    __syncthreads();
    if (tid < R_) {
        float a = bd0[tid];
        #pragma unroll
        for (int i = 0; i < R_; i++) a += h2[i]*wd0[i*R_+tid];
        land[tid] = a;
    }
    __syncthreads();
    float gt = *gate;
    for (int d = tid; d < D_; d += blockDim.x) {
        float a = topo_b[d];
        #pragma unroll
        for (int i = 0; i < R_; i++) a += land[i]*topo_w[i*D_+d];
        g_topo[b*D_+d] = gt*a;
    }
}

template<bool FIRST>
__global__ void ln_k(const float* __restrict__ a, const float* __restrict__ br,
                     const float* __restrict__ gamma, const float* __restrict__ beta,
                     float* __restrict__ out, __half* __restrict__ pack) {
    __shared__ float tv[D_];
    __shared__ float red[8];
    long r = blockIdx.x; int tid = threadIdx.x;
    float loc = 0.f;
    for (int d = tid; d < D_; d += 256) {
        float t = a[r*D_+d] + br[r*D_+d];
        if (FIRST) t += g_topo[(r>>9)*D_ + d];
        tv[d] = t; loc += t;
    }
    float mean = blockReduceSum256(loc, red) * (1.f/D_);
    float lv = 0.f;
    for (int d = tid; d < D_; d += 256) { float c = tv[d]-mean; lv += c*c; }
    float var = blockReduceSum256(lv, red) * (1.f/D_);
    float rs = rsqrtf(var + 1e-5f);
    for (int d = tid; d < D_; d += 256) {
        float o = (tv[d]-mean)*rs*gamma[d] + beta[d];
        out[r*D_+d] = o;
        if (FIRST) pack[r*D_+d] = __float2half_rn(o);
    }
}

// ================= host =================
template<class T> static T* symaddr(const void* sym) {
    void* p = nullptr; cudaGetSymbolAddress(&p, sym); return (T*)p;
}

extern "C" void kernel_launch(void* const* d_in, const int* in_sizes, int n_in,
                              void* d_out, int out_size) {
    const float* x      = (const float*)d_in[0];
    const int*   sidx   = (const int*)  d_in[1];
    const float* w1     = (const float*)d_in[2];
    const float* b1     = (const float*)d_in[3];
    const float* w2     = (const float*)d_in[4];
    const float* b2     = (const float*)d_in[5];
    const float* wd0    = (const float*)d_in[6];
    const float* bd0    = (const float*)d_in[7];
    const float* in_w   = (const float*)d_in[10];
    const float* in_b   = (const float*)d_in[11];
    const float* out_w  = (const float*)d_in[12];
    const float* out_b  = (const float*)d_in[13];
    const float* topo_w = (const float*)d_in[14];
    const float* topo_b = (const float*)d_in[15];
    const float* gate   = (const float*)d_in[16];
    const float* ln1_g  = (const float*)d_in[17];
    const float* ln1_b  = (const float*)d_in[18];
    const float* ln2_g  = (const float*)d_in[19];
    const float* ln2_b  = (const float*)d_in[20];
    const float* ffn_w1 = (const float*)d_in[21];
    const float* ffn_b1 = (const float*)d_in[22];
    const float* ffn_w2 = (const float*)d_in[23];
    const float* ffn_b2 = (const float*)d_in[24];
    float* out = (float*)d_out;

    auto p_xnorm = symaddr<float>(g_xnorm);
    auto p_dist  = symaddr<float>(g_dist);
    auto p_xp    = symaddr<__half>(g_xpack);
    auto p_qkvp  = symaddr<__half>(g_qkvpack);
    auto p_op    = symaddr<__half>(g_opack);
    auto p_attnP = symaddr<float>(g_attnP);
    auto p_x1    = symaddr<float>(g_x1);
    auto p_x1p   = symaddr<__half>(g_x1pack);
    auto p_hp    = symaddr<__half>(g_hpack);
    auto p_ffn2  = symaddr<float>(g_ffn2);
    auto p_wqkv  = symaddr<__half>(g_wqkvh);
    auto p_wout  = symaddr<__half>(g_wouth);
    auto p_wf1   = symaddr<__half>(g_wf1h);
    auto p_wf2   = symaddr<__half>(g_wf2h);

    constexpr int SM_BNN = 3*(128*72 + 64*136)*2;   // 105216
    constexpr int SM_NT  = 3*(128*72 + 64*72)*2;    // 82944
    constexpr int FSMEM  = 5*128*72*2;              // 92160
    cudaFuncSetAttribute(hgemm<128,0,true ,true ,false>, cudaFuncAttributeMaxDynamicSharedMemorySize, SM_BNN);
    cudaFuncSetAttribute(hgemm<128,0,false,true ,false>, cudaFuncAttributeMaxDynamicSharedMemorySize, SM_BNN);
    cudaFuncSetAttribute(hgemm<128,1,true ,true ,false>, cudaFuncAttributeMaxDynamicSharedMemorySize, SM_BNN);
    cudaFuncSetAttribute(hgemm<64, 3,false,false,true >, cudaFuncAttributeMaxDynamicSharedMemorySize, SM_NT);
    cudaFuncSetAttribute(flash_k, cudaFuncAttributeMaxDynamicSharedMemorySize, FSMEM);

    // one-time side stream + events (host-side resources only; no device allocs)
    static cudaStream_t sB = nullptr;
    static cudaEvent_t eFork = nullptr, eJoin = nullptr;
    if (!sB) {
        cudaStreamCreateWithFlags(&sB, cudaStreamNonBlocking);
        cudaEventCreateWithFlags(&eFork, cudaEventDisableTiming);
        cudaEventCreateWithFlags(&eJoin, cudaEventDisableTiming);
    }

    // ---- main stream: pack (also inits stats) ----
    xsplit_k<<<BS_,96>>>(x);
    cudaEventRecord(eFork, 0);

    // ---- side stream: LSH branch (cdist -> topk -> topo) ----
    cudaStreamWaitEvent(sB, eFork, 0);
    hgemm<64,3,false,false,true><<<dim3(2,4,B_),256,SM_NT,sB>>>(
        p_xp, p_xp, p_dist, nullptr,
        S_, D_, D_, D_, NS_,
        1, (long)S_*D_, 0, (long)S_*D_, 0, (long)S_*NS_, 0,
        0.f, p_xnorm, sidx);
    topk_stats_k<<<BS_/8,256,0,sB>>>();
    mlp_topo_k<<<B_,256,0,sB>>>(w1,b1,w2,b2,wd0,bd0,topo_w,topo_b,gate);
    cudaEventRecord(eJoin, sB);

    // ---- main stream: attention branch ----
    wconv_all_k<<<2304,256>>>(in_w, out_w, ffn_w1, ffn_w2);
    hgemm<128,0,true,true,false><<<dim3(18,64,1),256,SM_BNN>>>(
        p_xp, p_wqkv, p_qkvp, in_b,
        BS_, D_, D_, 3*D_, 3*D_,
        1, 0,0,0,0,0,0, 0.f, nullptr, nullptr);
    flash_k<<<dim3(4,Z_),256,FSMEM>>>(p_qkvp, p_op);
    hgemm<128,0,false,true,false><<<dim3(6,64,1),256,SM_BNN>>>(
        p_op, p_wout, p_attnP, out_b,
        BS_, D_, D_, D_, D_,
        1, 0,0,0,0,0,0, 0.f, nullptr, nullptr);

    // ---- join: LN1 needs g_topo ----
    cudaStreamWaitEvent(0, eJoin, 0);
    ln_k<true><<<BS_,256>>>(x, p_attnP, ln1_g, ln1_b, p_x1, p_x1p);

    // FFN
    hgemm<128,1,true,true,false><<<dim3(12,64,1),256,SM_BNN>>>(
        p_x1p, p_wf1, p_hp, ffn_b1,
        BS_, D_, D_, 2*D_, 2*D_,
        1, 0,0,0,0,0,0, 0.f, nullptr, nullptr);
    hgemm<128,0,false,true,false><<<dim3(6,64,1),256,SM_BNN>>>(
        p_hp, p_wf2, p_ffn2, ffn_b2,
        BS_, 2*D_, 2*D_, D_, D_,
        1, 0,0,0,0,0,0, 0.f, nullptr, nullptr);

    ln_k<false><<<BS_,256>>>(p_x1, p_ffn2, ln2_g, ln2_b, out, nullptr);
}